// round 1
// baseline (speedup 1.0000x reference)
#include <cuda_runtime.h>
#include <cuda_fp16.h>
#include <cstdint>

#define SA 136           // smem stride (halves) for activations
#define SW 136           // smem stride (halves) for weights
#define NTHREADS 256

#define B_ 512
#define LEAVES 1024
#define NINT 1023

// Weight storage (transposed [N][K], fp16 hi/lo split), filled by prep kernel
// leaf: L0 128x64=8192, L1..L4 4*16384, L5 40x128=5120  -> 78848
// int : L0 128x112=14336, L1..L4 4*16384, L5 40x128=5120 -> 84992
__device__ __half g_leaf_Wh[78848];
__device__ __half g_leaf_Wl[78848];
__device__ __half g_int_Wh[84992];
__device__ __half g_int_Wl[84992];
__device__ float  g_leaf_bias[768];   // 6 layers x 128 (padded)
__device__ float  g_int_bias[768];

// Ping-pong activation buffers for the tree (fp32, 33 channels per node)
__device__ float g_curA[(size_t)B_ * LEAVES * 33];   // 1024 nodes/batch
__device__ float g_curB[(size_t)B_ * 512 * 33];      // 512 nodes/batch

// ---------------------------------------------------------------------------
// Prep: convert & transpose all weights to fp16 hi/lo, pad, pack biases.
// ---------------------------------------------------------------------------
__global__ void prep_kernel(
    const float* __restrict__ lWin,  const float* __restrict__ lbin,
    const float* __restrict__ lWhid, const float* __restrict__ lbhid,
    const float* __restrict__ lWout, const float* __restrict__ lbout,
    const float* __restrict__ iWin,  const float* __restrict__ ibin,
    const float* __restrict__ iWhid, const float* __restrict__ ibhid,
    const float* __restrict__ iWout, const float* __restrict__ ibout)
{
    const int total = 78848 + 84992 + 1536;
    for (int i = blockIdx.x * blockDim.x + threadIdx.x; i < total;
         i += gridDim.x * blockDim.x) {
        if (i < 78848) {
            // leaf weights
            float v;
            if (i < 8192) {                 // L0: [128][64] <- lWin[k*128+n]
                int n = i >> 6, k = i & 63;
                v = lWin[k * 128 + n];
            } else if (i < 73728) {         // L1..L4: [128][128]
                int j = i - 8192;
                int l = j >> 14;            // 0..3
                int w = j & 16383;
                int n = w >> 7, k = w & 127;
                v = lWhid[l * 16384 + k * 128 + n];
            } else {                        // L5: [40][128] <- lWout[k*33+n]
                int j = i - 73728;
                int n = j >> 7, k = j & 127;
                v = (n < 33) ? lWout[k * 33 + n] : 0.f;
            }
            __half h = __float2half_rn(v);
            __half lo = __float2half_rn(v - __half2float(h));
            g_leaf_Wh[i] = h; g_leaf_Wl[i] = lo;
        } else if (i < 78848 + 84992) {
            // int weights
            int i2 = i - 78848;
            float v;
            if (i2 < 14336) {               // L0: [128][112] <- iWin[k*128+n], k<98
                int n = i2 / 112, k = i2 - n * 112;
                v = (k < 98) ? iWin[k * 128 + n] : 0.f;
            } else if (i2 < 79872) {
                int j = i2 - 14336;
                int l = j >> 14;
                int w = j & 16383;
                int n = w >> 7, k = w & 127;
                v = iWhid[l * 16384 + k * 128 + n];
            } else {
                int j = i2 - 79872;
                int n = j >> 7, k = j & 127;
                v = (n < 33) ? iWout[k * 33 + n] : 0.f;
            }
            __half h = __float2half_rn(v);
            __half lo = __float2half_rn(v - __half2float(h));
            g_int_Wh[i2] = h; g_int_Wl[i2] = lo;
        } else {
            int i3 = i - 78848 - 84992;     // 0..1535
            int unit = i3 >> 9 >= 1 ? 1 : 0; // i3<768 -> leaf
            int j = (i3 < 768) ? i3 : i3 - 768;
            int l = j >> 7, c = j & 127;
            float v;
            if (i3 < 768) {
                if (l == 0)      v = lbin[c];
                else if (l < 5)  v = lbhid[(l - 1) * 128 + c];
                else             v = (c < 33) ? lbout[c] : 0.f;
                g_leaf_bias[j] = v;
            } else {
                if (l == 0)      v = ibin[c];
                else if (l < 5)  v = ibhid[(l - 1) * 128 + c];
                else             v = (c < 33) ? ibout[c] : 0.f;
                g_int_bias[j] = v;
            }
            (void)unit;
        }
    }
}

// ---------------------------------------------------------------------------
// m16n8k16 fp16 MMA with fp32 accumulators
// ---------------------------------------------------------------------------
__device__ __forceinline__ void mma16816(float* c, const uint32_t* a,
                                         uint32_t b0, uint32_t b1)
{
    asm volatile(
        "mma.sync.aligned.m16n8k16.row.col.f32.f16.f16.f32 "
        "{%0,%1,%2,%3}, {%4,%5,%6,%7}, {%8,%9}, {%0,%1,%2,%3};\n"
        : "+f"(c[0]), "+f"(c[1]), "+f"(c[2]), "+f"(c[3])
        : "r"(a[0]), "r"(a[1]), "r"(a[2]), "r"(a[3]), "r"(b0), "r"(b1));
}

// ---------------------------------------------------------------------------
// Run a 6-layer MLP for 128 rows held in smem (hi/lo split, 3-MMA fp32 emu).
// Layers: l=0: Kp0 -> 128, l=1..4: 128 -> 128 (ReLU), l=5: 128 -> 40(pad of 33)
// Output layer: writes fp32 rows of 33 to gout, or only channel 0 to dfinal.
// ---------------------------------------------------------------------------
__device__ __forceinline__ void run_unit(
    __half* sAh, __half* sAl, __half* sWh, __half* sWl,
    const __half* gWh, const __half* gWl, const float* gbias,
    int Kp0, float* gout, float* dfinal, int row0)
{
    const int tid  = threadIdx.x;
    const int warp = tid >> 5;
    const int lane = tid & 31;
    const int wm = warp >> 2;      // 0..1  (row block of 64)
    const int wn = warp & 3;       // 0..3  (col block of 32)
    const int gid = lane >> 2;     // 0..7
    const int tig = lane & 3;      // 0..3

    int woff = 0;
    for (int l = 0; l < 6; ++l) {
        const int Kp = (l == 0) ? Kp0 : 128;
        const int Np = (l < 5) ? 128 : 40;

        // ---- stage weights (hi & lo) into smem ----
        {
            const __half* Wh = gWh + woff;
            const __half* Wl = gWl + woff;
            const int kv = Kp >> 3;              // uint4 per row
            const int nv = Np * kv;
            for (int i = tid; i < nv; i += NTHREADS) {
                int r = i / kv;
                int c = (i - r * kv) << 3;
                *(uint4*)(sWh + r * SW + c) = *(const uint4*)(Wh + r * Kp + c);
                *(uint4*)(sWl + r * SW + c) = *(const uint4*)(Wl + r * Kp + c);
            }
        }
        woff += Np * Kp;
        __syncthreads();

        // ---- MMA: 3 passes (Ah*Wh + Ah*Wl + Al*Wh) ----
        float C[4][4][4];
        #pragma unroll
        for (int mt = 0; mt < 4; ++mt)
            #pragma unroll
            for (int nt = 0; nt < 4; ++nt)
                #pragma unroll
                for (int q = 0; q < 4; ++q) C[mt][nt][q] = 0.f;

        int nt_count = (Np - wn * 32 + 7) >> 3;
        if (nt_count < 0) nt_count = 0;
        if (nt_count > 4) nt_count = 4;

        for (int p = 0; p < 3; ++p) {
            const __half* Ap = (p < 2) ? sAh : sAl;
            const __half* Wp = (p == 1) ? sWl : sWh;
            for (int k0 = 0; k0 < Kp; k0 += 16) {
                uint32_t a[4][4];
                #pragma unroll
                for (int mt = 0; mt < 4; ++mt) {
                    const __half* base = Ap + (wm * 64 + mt * 16 + gid) * SA + k0 + tig * 2;
                    a[mt][0] = *(const uint32_t*)(base);
                    a[mt][1] = *(const uint32_t*)(base + 8 * SA);
                    a[mt][2] = *(const uint32_t*)(base + 8);
                    a[mt][3] = *(const uint32_t*)(base + 8 * SA + 8);
                }
                #pragma unroll
                for (int nt = 0; nt < 4; ++nt) {
                    if (nt < nt_count) {
                        const __half* bb = Wp + (wn * 32 + nt * 8 + gid) * SW + k0 + tig * 2;
                        uint32_t b0 = *(const uint32_t*)(bb);
                        uint32_t b1 = *(const uint32_t*)(bb + 8);
                        #pragma unroll
                        for (int mt = 0; mt < 4; ++mt)
                            mma16816(C[mt][nt], a[mt], b0, b1);
                    }
                }
            }
        }
        __syncthreads();

        // ---- epilogue ----
        if (l < 5) {
            #pragma unroll
            for (int mt = 0; mt < 4; ++mt) {
                #pragma unroll
                for (int nt = 0; nt < 4; ++nt) {
                    if (nt < nt_count) {
                        int r  = wm * 64 + mt * 16 + gid;
                        int cb = wn * 32 + nt * 8 + tig * 2;
                        float bb0 = gbias[l * 128 + cb];
                        float bb1 = gbias[l * 128 + cb + 1];
                        float v00 = fmaxf(C[mt][nt][0] + bb0, 0.f);
                        float v01 = fmaxf(C[mt][nt][1] + bb1, 0.f);
                        float v10 = fmaxf(C[mt][nt][2] + bb0, 0.f);
                        float v11 = fmaxf(C[mt][nt][3] + bb1, 0.f);
                        __half h00 = __float2half_rn(v00), h01 = __float2half_rn(v01);
                        __half h10 = __float2half_rn(v10), h11 = __float2half_rn(v11);
                        __half e00 = __float2half_rn(v00 - __half2float(h00));
                        __half e01 = __float2half_rn(v01 - __half2float(h01));
                        __half e10 = __float2half_rn(v10 - __half2float(h10));
                        __half e11 = __float2half_rn(v11 - __half2float(h11));
                        *(__half2*)(sAh + r * SA + cb)       = __halves2half2(h00, h01);
                        *(__half2*)(sAh + (r + 8) * SA + cb) = __halves2half2(h10, h11);
                        *(__half2*)(sAl + r * SA + cb)       = __halves2half2(e00, e01);
                        *(__half2*)(sAl + (r + 8) * SA + cb) = __halves2half2(e10, e11);
                    }
                }
            }
            __syncthreads();
        } else {
            // output layer (no ReLU)
            #pragma unroll
            for (int mt = 0; mt < 4; ++mt) {
                #pragma unroll
                for (int nt = 0; nt < 4; ++nt) {
                    if (nt < nt_count) {
                        int r  = wm * 64 + mt * 16 + gid;
                        int cb = wn * 32 + nt * 8 + tig * 2;
                        float bb0 = gbias[640 + cb];
                        float bb1 = gbias[640 + cb + 1];
                        float v00 = C[mt][nt][0] + bb0;
                        float v01 = C[mt][nt][1] + bb1;
                        float v10 = C[mt][nt][2] + bb0;
                        float v11 = C[mt][nt][3] + bb1;
                        if (dfinal) {
                            if (cb == 0) {
                                dfinal[row0 + r]     = v00;
                                dfinal[row0 + r + 8] = v10;
                            }
                        } else {
                            size_t ro = (size_t)(row0 + r) * 33;
                            size_t r8 = (size_t)(row0 + r + 8) * 33;
                            if (cb < 33)     { gout[ro + cb]     = v00; gout[r8 + cb]     = v10; }
                            if (cb + 1 < 33) { gout[ro + cb + 1] = v01; gout[r8 + cb + 1] = v11; }
                        }
                    }
                }
            }
        }
    }
}

// ---------------------------------------------------------------------------
// Leaf kernel: 128 rows/CTA of leaf_feat (K0=64) -> cur (33 ch, fp32)
// ---------------------------------------------------------------------------
__global__ void __launch_bounds__(NTHREADS, 1)
leaf_kernel(const float* __restrict__ leaf_feat, float* __restrict__ curOut)
{
    extern __shared__ __half smem[];
    __half* sAh = smem;
    __half* sAl = sAh + 128 * SA;
    __half* sWh = sAl + 128 * SA;
    __half* sWl = sWh + 128 * SW;

    const int row0 = blockIdx.x * 128;

    for (int i = threadIdx.x; i < 128 * 16; i += NTHREADS) {
        int r = i >> 4, c4 = i & 15;
        float4 v = ((const float4*)(leaf_feat + (size_t)(row0 + r) * 64))[c4];
        int c = c4 * 4;
        __half h0 = __float2half_rn(v.x), h1 = __float2half_rn(v.y);
        __half h2 = __float2half_rn(v.z), h3 = __float2half_rn(v.w);
        __half e0 = __float2half_rn(v.x - __half2float(h0));
        __half e1 = __float2half_rn(v.y - __half2float(h1));
        __half e2 = __float2half_rn(v.z - __half2float(h2));
        __half e3 = __float2half_rn(v.w - __half2float(h3));
        *(__half2*)(sAh + r * SA + c)     = __halves2half2(h0, h1);
        *(__half2*)(sAh + r * SA + c + 2) = __halves2half2(h2, h3);
        *(__half2*)(sAl + r * SA + c)     = __halves2half2(e0, e1);
        *(__half2*)(sAl + r * SA + c + 2) = __halves2half2(e2, e3);
    }
    __syncthreads();

    run_unit(sAh, sAl, sWh, sWl, g_leaf_Wh, g_leaf_Wl, g_leaf_bias,
             64, curOut, nullptr, row0);
}

// ---------------------------------------------------------------------------
// Tree-level kernel: builds [feat(32) | child0(33) | child1(33) | pad] rows
// (K0=112) and runs the int MLP. If dfinal != nullptr, writes channel 0 only.
// ---------------------------------------------------------------------------
__global__ void __launch_bounds__(NTHREADS, 1)
int_kernel(const float* __restrict__ int_feat, const float* __restrict__ prev,
           float* __restrict__ curOut, int log2n, float* dfinal)
{
    extern __shared__ __half smem[];
    __half* sAh = smem;
    __half* sAl = sAh + 128 * SA;
    __half* sWh = sAl + 128 * SA;
    __half* sWl = sWh + 128 * SW;

    const int row0 = blockIdx.x * 128;
    const int n = 1 << log2n;

    for (int i = threadIdx.x; i < 128 * 112; i += NTHREADS) {
        int r = i / 112, c = i - r * 112;
        int rowg = row0 + r;
        int b  = rowg >> log2n;
        int ii = rowg & (n - 1);
        float v;
        if (c < 32) {
            v = int_feat[((size_t)b * NINT + (n - 1) + ii) * 32 + c];
        } else if (c < 98) {
            v = prev[((size_t)b * (n << 1) + (ii << 1)) * 33 + (c - 32)];
        } else {
            v = 0.f;
        }
        __half h = __float2half_rn(v);
        __half e = __float2half_rn(v - __half2float(h));
        sAh[r * SA + c] = h;
        sAl[r * SA + c] = e;
    }
    __syncthreads();

    run_unit(sAh, sAl, sWh, sWl, g_int_Wh, g_int_Wl, g_int_bias,
             112, curOut, dfinal, row0);
}

// ---------------------------------------------------------------------------
extern "C" void kernel_launch(void* const* d_in, const int* in_sizes, int n_in,
                              void* d_out, int out_size)
{
    const float* leaf_feat = (const float*)d_in[0];
    const float* int_feat  = (const float*)d_in[1];
    const float* lWin  = (const float*)d_in[2];
    const float* lbin  = (const float*)d_in[3];
    const float* lWhid = (const float*)d_in[4];
    const float* lbhid = (const float*)d_in[5];
    const float* lWout = (const float*)d_in[6];
    const float* lbout = (const float*)d_in[7];
    const float* iWin  = (const float*)d_in[8];
    const float* ibin  = (const float*)d_in[9];
    const float* iWhid = (const float*)d_in[10];
    const float* ibhid = (const float*)d_in[11];
    const float* iWout = (const float*)d_in[12];
    const float* ibout = (const float*)d_in[13];
    float* out = (float*)d_out;

    const int smem_bytes = (128 * SA * 2 + 128 * SW * 2) * (int)sizeof(__half); // 139264
    cudaFuncSetAttribute(leaf_kernel, cudaFuncAttributeMaxDynamicSharedMemorySize, smem_bytes);
    cudaFuncSetAttribute(int_kernel,  cudaFuncAttributeMaxDynamicSharedMemorySize, smem_bytes);

    float *curA = nullptr, *curB = nullptr;
    cudaGetSymbolAddress((void**)&curA, g_curA);
    cudaGetSymbolAddress((void**)&curB, g_curB);

    prep_kernel<<<256, 256>>>(lWin, lbin, lWhid, lbhid, lWout, lbout,
                              iWin, ibin, iWhid, ibhid, iWout, ibout);

    // Leaf stage: 512*1024 rows
    leaf_kernel<<<(B_ * LEAVES) / 128, NTHREADS, smem_bytes>>>(leaf_feat, curA);

    // Tree reduction, levels d = 9 .. 1
    float* pin = curA;
    float* pout = curB;
    for (int d = 9; d >= 1; --d) {
        int rows = B_ << d;
        int_kernel<<<rows / 128, NTHREADS, smem_bytes>>>(int_feat, pin, pout, d, nullptr);
        float* t = pin; pin = pout; pout = t;
    }
    // Final level d = 0: 512 rows, write channel 0 to d_out
    int_kernel<<<B_ / 128, NTHREADS, smem_bytes>>>(int_feat, pin, pout, 0, out);
}

// round 2
// speedup vs baseline: 1.3460x; 1.3460x over previous
#include <cuda_runtime.h>
#include <cuda_fp16.h>
#include <cstdint>

#define SA 136           // smem stride (halves) for activations
#define SW 136           // smem stride (halves) for weights
#define NT 512           // 16 warps

#define B_ 512
#define LEAVES 1024
#define NINT 1023

// Weight storage (transposed [N][K], fp16 hi/lo split), filled by prep kernel
// leaf: L0 128x64=8192, L1..L4 4*16384, L5 40x128=5120  -> 78848
// int : L0 128x112=14336, L1..L4 4*16384, L5 40x128=5120 -> 84992
__device__ __align__(16) __half g_leaf_Wh[78848];
__device__ __align__(16) __half g_leaf_Wl[78848];
__device__ __align__(16) __half g_int_Wh[84992];
__device__ __align__(16) __half g_int_Wl[84992];
__device__ float  g_leaf_bias[768];   // 6 layers x 128 (padded)
__device__ float  g_int_bias[768];

// Ping-pong activation buffers for the tree (fp32, 33 channels per node)
__device__ float g_curA[(size_t)B_ * LEAVES * 33];
__device__ float g_curB[(size_t)B_ * 512 * 33];

// ---------------------------------------------------------------------------
// Prep: convert & transpose all weights to fp16 hi/lo, pad, pack biases.
// ---------------------------------------------------------------------------
__global__ void prep_kernel(
    const float* __restrict__ lWin,  const float* __restrict__ lbin,
    const float* __restrict__ lWhid, const float* __restrict__ lbhid,
    const float* __restrict__ lWout, const float* __restrict__ lbout,
    const float* __restrict__ iWin,  const float* __restrict__ ibin,
    const float* __restrict__ iWhid, const float* __restrict__ ibhid,
    const float* __restrict__ iWout, const float* __restrict__ ibout)
{
    const int total = 78848 + 84992 + 1536;
    for (int i = blockIdx.x * blockDim.x + threadIdx.x; i < total;
         i += gridDim.x * blockDim.x) {
        if (i < 78848) {
            float v;
            if (i < 8192) {                 // L0: [128][64] <- lWin[k*128+n]
                int n = i >> 6, k = i & 63;
                v = lWin[k * 128 + n];
            } else if (i < 73728) {         // L1..L4: [128][128]
                int j = i - 8192;
                int l = j >> 14;
                int w = j & 16383;
                int n = w >> 7, k = w & 127;
                v = lWhid[l * 16384 + k * 128 + n];
            } else {                        // L5: [40][128] <- lWout[k*33+n]
                int j = i - 73728;
                int n = j >> 7, k = j & 127;
                v = (n < 33) ? lWout[k * 33 + n] : 0.f;
            }
            __half h = __float2half_rn(v);
            __half lo = __float2half_rn(v - __half2float(h));
            g_leaf_Wh[i] = h; g_leaf_Wl[i] = lo;
        } else if (i < 78848 + 84992) {
            int i2 = i - 78848;
            float v;
            if (i2 < 14336) {               // L0: [128][112] <- iWin[k*128+n], k<98
                int n = i2 / 112, k = i2 - n * 112;
                v = (k < 98) ? iWin[k * 128 + n] : 0.f;
            } else if (i2 < 79872) {
                int j = i2 - 14336;
                int l = j >> 14;
                int w = j & 16383;
                int n = w >> 7, k = w & 127;
                v = iWhid[l * 16384 + k * 128 + n];
            } else {
                int j = i2 - 79872;
                int n = j >> 7, k = j & 127;
                v = (n < 33) ? iWout[k * 33 + n] : 0.f;
            }
            __half h = __float2half_rn(v);
            __half lo = __float2half_rn(v - __half2float(h));
            g_int_Wh[i2] = h; g_int_Wl[i2] = lo;
        } else {
            int i3 = i - 78848 - 84992;     // 0..1535
            int j = (i3 < 768) ? i3 : i3 - 768;
            int l = j >> 7, c = j & 127;
            float v;
            if (i3 < 768) {
                if (l == 0)      v = lbin[c];
                else if (l < 5)  v = lbhid[(l - 1) * 128 + c];
                else             v = (c < 33) ? lbout[c] : 0.f;
                g_leaf_bias[j] = v;
            } else {
                if (l == 0)      v = ibin[c];
                else if (l < 5)  v = ibhid[(l - 1) * 128 + c];
                else             v = (c < 33) ? ibout[c] : 0.f;
                g_int_bias[j] = v;
            }
        }
    }
}

// ---------------------------------------------------------------------------
// PTX helpers
// ---------------------------------------------------------------------------
__device__ __forceinline__ void mma16816(float* c, const uint32_t* a,
                                         uint32_t b0, uint32_t b1)
{
    asm volatile(
        "mma.sync.aligned.m16n8k16.row.col.f32.f16.f16.f32 "
        "{%0,%1,%2,%3}, {%4,%5,%6,%7}, {%8,%9}, {%0,%1,%2,%3};\n"
        : "+f"(c[0]), "+f"(c[1]), "+f"(c[2]), "+f"(c[3])
        : "r"(a[0]), "r"(a[1]), "r"(a[2]), "r"(a[3]), "r"(b0), "r"(b1));
}

__device__ __forceinline__ void ldsm4(uint32_t* r, uint32_t addr)
{
    asm volatile("ldmatrix.sync.aligned.m8n8.x4.shared.b16 {%0,%1,%2,%3}, [%4];"
                 : "=r"(r[0]), "=r"(r[1]), "=r"(r[2]), "=r"(r[3]) : "r"(addr));
}

__device__ __forceinline__ void cpa16(uint32_t dst, const void* src)
{
    asm volatile("cp.async.cg.shared.global [%0], [%1], 16;" :: "r"(dst), "l"(src));
}
__device__ __forceinline__ void cpa_commit() { asm volatile("cp.async.commit_group;"); }

// stage one layer's weights (hi+lo) via cp.async
__device__ __forceinline__ void stage_weights(
    uint32_t sWh, uint32_t sWl, const __half* gWh, const __half* gWl,
    int Np, int kv /* = Kp/8 */)
{
    const int Kp = kv << 3;
    const int nchunks = Np * kv;
    for (int i = threadIdx.x; i < nchunks; i += NT) {
        int r = i / kv;
        int c = (i - r * kv) << 3;
        uint32_t off = (uint32_t)(r * SW + c) * 2u;
        cpa16(sWh + off, gWh + r * Kp + c);
        cpa16(sWl + off, gWl + r * Kp + c);
    }
}

// ---------------------------------------------------------------------------
// Run a 6-layer MLP for 128 rows held in smem (hi/lo split, 3-MMA fp32 emu).
// 16 warps: warp (wm,wn) owns a 32x32 tile. cp.async double-buffered weights.
// ---------------------------------------------------------------------------
__device__ __forceinline__ void run_unit(
    __half* smem, const __half* gWh, const __half* gWl, const float* gbias,
    int Kp0, float* gout, float* dfinal, int row0)
{
    __half* sAh = smem;
    __half* sAl = smem + 17408;
    const uint32_t smem_u = (uint32_t)__cvta_generic_to_shared(smem);
    const uint32_t uAh = smem_u;
    const uint32_t uAl = smem_u + 17408u * 2u;
    const uint32_t uW0 = smem_u + 34816u * 2u;   // buf0: Wh then Wl
    const uint32_t uW1 = smem_u + 69632u * 2u;   // buf1

    const int tid  = threadIdx.x;
    const int warp = tid >> 5;
    const int lane = tid & 31;
    const int wm = warp >> 2;      // 0..3 (32-row block)
    const int wn = warp & 3;       // 0..3 (32-col block)
    const int gid = lane >> 2;
    const int tig = lane & 3;

    // lane-dependent ldmatrix offsets (in halves)
    // A: rows R + (lane&15), col (lane>>4)*8
    const int aRow = wm * 32 + (lane & 15);
    const int aCol = (lane >> 4) << 3;
    const uint32_t offA0 = (uint32_t)(aRow * SA + aCol) * 2u;          // mt=0
    const uint32_t offA1 = offA0 + (uint32_t)(16 * SA) * 2u;           // mt=1
    // W: n = wn*32 + pair*16 + (lane>>4)*8 + (lane&7), col ((lane>>3)&1)*8
    const int wRowBase = wn * 32 + ((lane >> 4) << 3) + (lane & 7);
    const int wCol = ((lane >> 3) & 1) << 3;
    const uint32_t offW0 = (uint32_t)(wRowBase * SW + wCol) * 2u;      // pair=0
    const uint32_t offW1 = offW0 + (uint32_t)(16 * SW) * 2u;           // pair=1

    const int KpA[6] = {Kp0, 128, 128, 128, 128, 128};
    const int NpA[6] = {128, 128, 128, 128, 128, 40};

    // prologue: stage layer 0 into buf 0
    stage_weights(uW0, uW0 + 17408u * 2u, gWh, gWl, 128, Kp0 >> 3);
    cpa_commit();

    int woff = 128 * Kp0;
    for (int l = 0; l < 6; ++l) {
        const int Kp = KpA[l];
        const int Np = NpA[l];
        const uint32_t uWbuf = (l & 1) ? uW1 : uW0;
        const uint32_t uWh = uWbuf;
        const uint32_t uWl = uWbuf + 17408u * 2u;

        if (l < 5) {
            const uint32_t uNext = (l & 1) ? uW0 : uW1;
            stage_weights(uNext, uNext + 17408u * 2u,
                          gWh + woff, gWl + woff, NpA[l + 1], KpA[l + 1] >> 3);
            cpa_commit();
            woff += NpA[l + 1] * KpA[l + 1];
            asm volatile("cp.async.wait_group 1;");
        } else {
            asm volatile("cp.async.wait_group 0;");
        }
        __syncthreads();

        // tiles this warp owns in N
        int nt_count = (Np - wn * 32 + 7) >> 3;
        if (nt_count < 0) nt_count = 0;
        if (nt_count > 4) nt_count = 4;
        const int pair_count = (nt_count + 1) >> 1;

        float C[2][4][4];
        #pragma unroll
        for (int mt = 0; mt < 2; ++mt)
            #pragma unroll
            for (int nt = 0; nt < 4; ++nt)
                #pragma unroll
                for (int q = 0; q < 4; ++q) C[mt][nt][q] = 0.f;

        if (nt_count > 0) {
            uint32_t aAh0 = uAh + offA0, aAh1 = uAh + offA1;
            uint32_t aAl0 = uAl + offA0, aAl1 = uAl + offA1;
            uint32_t aWh0 = uWh + offW0, aWh1 = uWh + offW1;
            uint32_t aWl0 = uWl + offW0, aWl1 = uWl + offW1;

            for (int k0 = 0; k0 < Kp; k0 += 16) {
                uint32_t ah[2][4], al[2][4];
                uint32_t whf[2][4], wlf[2][4];
                ldsm4(ah[0], aAh0); ldsm4(ah[1], aAh1);
                ldsm4(al[0], aAl0); ldsm4(al[1], aAl1);
                ldsm4(whf[0], aWh0); ldsm4(wlf[0], aWl0);
                if (pair_count > 1) { ldsm4(whf[1], aWh1); ldsm4(wlf[1], aWl1); }

                #pragma unroll
                for (int nt = 0; nt < 4; ++nt) {
                    if (nt < nt_count) {
                        const int p = nt >> 1, q = (nt & 1) << 1;
                        uint32_t b0h = whf[p][q], b1h = whf[p][q + 1];
                        uint32_t b0l = wlf[p][q], b1l = wlf[p][q + 1];
                        #pragma unroll
                        for (int mt = 0; mt < 2; ++mt) {
                            mma16816(C[mt][nt], ah[mt], b0h, b1h);
                            mma16816(C[mt][nt], ah[mt], b0l, b1l);
                            mma16816(C[mt][nt], al[mt], b0h, b1h);
                        }
                    }
                }
                aAh0 += 32; aAh1 += 32; aAl0 += 32; aAl1 += 32;
                aWh0 += 32; aWh1 += 32; aWl0 += 32; aWl1 += 32;
            }
        }
        __syncthreads();

        // ---- epilogue ----
        if (l < 5) {
            #pragma unroll
            for (int mt = 0; mt < 2; ++mt) {
                #pragma unroll
                for (int nt = 0; nt < 4; ++nt) {
                    if (nt < nt_count) {
                        int r  = wm * 32 + mt * 16 + gid;
                        int cb = wn * 32 + nt * 8 + tig * 2;
                        float bb0 = gbias[l * 128 + cb];
                        float bb1 = gbias[l * 128 + cb + 1];
                        float v00 = fmaxf(C[mt][nt][0] + bb0, 0.f);
                        float v01 = fmaxf(C[mt][nt][1] + bb1, 0.f);
                        float v10 = fmaxf(C[mt][nt][2] + bb0, 0.f);
                        float v11 = fmaxf(C[mt][nt][3] + bb1, 0.f);
                        __half h00 = __float2half_rn(v00), h01 = __float2half_rn(v01);
                        __half h10 = __float2half_rn(v10), h11 = __float2half_rn(v11);
                        __half e00 = __float2half_rn(v00 - __half2float(h00));
                        __half e01 = __float2half_rn(v01 - __half2float(h01));
                        __half e10 = __float2half_rn(v10 - __half2float(h10));
                        __half e11 = __float2half_rn(v11 - __half2float(h11));
                        *(__half2*)(sAh + r * SA + cb)        = __halves2half2(h00, h01);
                        *(__half2*)(sAh + (r + 8) * SA + cb)  = __halves2half2(h10, h11);
                        *(__half2*)(sAl + r * SA + cb)        = __halves2half2(e00, e01);
                        *(__half2*)(sAl + (r + 8) * SA + cb)  = __halves2half2(e10, e11);
                    }
                }
            }
        } else {
            #pragma unroll
            for (int mt = 0; mt < 2; ++mt) {
                #pragma unroll
                for (int nt = 0; nt < 4; ++nt) {
                    if (nt < nt_count) {
                        int r  = wm * 32 + mt * 16 + gid;
                        int cb = wn * 32 + nt * 8 + tig * 2;
                        float bb0 = gbias[640 + cb];
                        float bb1 = gbias[640 + cb + 1];
                        float v00 = C[mt][nt][0] + bb0;
                        float v01 = C[mt][nt][1] + bb1;
                        float v10 = C[mt][nt][2] + bb0;
                        float v11 = C[mt][nt][3] + bb1;
                        if (dfinal) {
                            if (cb == 0) {
                                dfinal[row0 + r]     = v00;
                                dfinal[row0 + r + 8] = v10;
                            }
                        } else {
                            size_t ro = (size_t)(row0 + r) * 33;
                            size_t r8 = (size_t)(row0 + r + 8) * 33;
                            if (cb < 33)     { gout[ro + cb]     = v00; gout[r8 + cb]     = v10; }
                            if (cb + 1 < 33) { gout[ro + cb + 1] = v01; gout[r8 + cb + 1] = v11; }
                        }
                    }
                }
            }
        }
    }
}

// ---------------------------------------------------------------------------
// Leaf kernel: 128 rows/CTA of leaf_feat (K0=64) -> cur (33 ch, fp32)
// ---------------------------------------------------------------------------
__global__ void __launch_bounds__(NT, 1)
leaf_kernel(const float* __restrict__ leaf_feat, float* __restrict__ curOut)
{
    extern __shared__ __half smem[];
    __half* sAh = smem;
    __half* sAl = smem + 17408;

    const int row0 = blockIdx.x * 128;

    for (int i = threadIdx.x; i < 128 * 16; i += NT) {
        int r = i >> 4, c4 = i & 15;
        float4 v = ((const float4*)(leaf_feat + (size_t)(row0 + r) * 64))[c4];
        int c = c4 * 4;
        __half h0 = __float2half_rn(v.x), h1 = __float2half_rn(v.y);
        __half h2 = __float2half_rn(v.z), h3 = __float2half_rn(v.w);
        __half e0 = __float2half_rn(v.x - __half2float(h0));
        __half e1 = __float2half_rn(v.y - __half2float(h1));
        __half e2 = __float2half_rn(v.z - __half2float(h2));
        __half e3 = __float2half_rn(v.w - __half2float(h3));
        *(__half2*)(sAh + r * SA + c)     = __halves2half2(h0, h1);
        *(__half2*)(sAh + r * SA + c + 2) = __halves2half2(h2, h3);
        *(__half2*)(sAl + r * SA + c)     = __halves2half2(e0, e1);
        *(__half2*)(sAl + r * SA + c + 2) = __halves2half2(e2, e3);
    }

    run_unit(smem, g_leaf_Wh, g_leaf_Wl, g_leaf_bias, 64, curOut, nullptr, row0);
}

// ---------------------------------------------------------------------------
// Tree-level kernel: builds [feat(32) | child0(33) | child1(33) | pad] rows
// ---------------------------------------------------------------------------
__global__ void __launch_bounds__(NT, 1)
int_kernel(const float* __restrict__ int_feat, const float* __restrict__ prev,
           float* __restrict__ curOut, int log2n, float* dfinal)
{
    extern __shared__ __half smem[];
    __half* sAh = smem;
    __half* sAl = smem + 17408;

    const int row0 = blockIdx.x * 128;
    const int n = 1 << log2n;

    for (int i = threadIdx.x; i < 128 * 112; i += NT) {
        int r = i / 112, c = i - r * 112;
        int rowg = row0 + r;
        int b  = rowg >> log2n;
        int ii = rowg & (n - 1);
        float v;
        if (c < 32) {
            v = int_feat[((size_t)b * NINT + (n - 1) + ii) * 32 + c];
        } else if (c < 98) {
            v = prev[((size_t)b * (n << 1) + (ii << 1)) * 33 + (c - 32)];
        } else {
            v = 0.f;
        }
        __half h = __float2half_rn(v);
        __half e = __float2half_rn(v - __half2float(h));
        sAh[r * SA + c] = h;
        sAl[r * SA + c] = e;
    }

    run_unit(smem, g_int_Wh, g_int_Wl, g_int_bias, 112, curOut, dfinal, row0);
}

// ---------------------------------------------------------------------------
extern "C" void kernel_launch(void* const* d_in, const int* in_sizes, int n_in,
                              void* d_out, int out_size)
{
    const float* leaf_feat = (const float*)d_in[0];
    const float* int_feat  = (const float*)d_in[1];
    const float* lWin  = (const float*)d_in[2];
    const float* lbin  = (const float*)d_in[3];
    const float* lWhid = (const float*)d_in[4];
    const float* lbhid = (const float*)d_in[5];
    const float* lWout = (const float*)d_in[6];
    const float* lbout = (const float*)d_in[7];
    const float* iWin  = (const float*)d_in[8];
    const float* ibin  = (const float*)d_in[9];
    const float* iWhid = (const float*)d_in[10];
    const float* ibhid = (const float*)d_in[11];
    const float* iWout = (const float*)d_in[12];
    const float* ibout = (const float*)d_in[13];
    float* out = (float*)d_out;

    // smem: act (2*17408) + weights double-buffered (2*34816) halves
    const int smem_bytes = (2 * 17408 + 2 * 34816) * (int)sizeof(__half); // 208896
    cudaFuncSetAttribute(leaf_kernel, cudaFuncAttributeMaxDynamicSharedMemorySize, smem_bytes);
    cudaFuncSetAttribute(int_kernel,  cudaFuncAttributeMaxDynamicSharedMemorySize, smem_bytes);

    float *curA = nullptr, *curB = nullptr;
    cudaGetSymbolAddress((void**)&curA, g_curA);
    cudaGetSymbolAddress((void**)&curB, g_curB);

    prep_kernel<<<256, 256>>>(lWin, lbin, lWhid, lbhid, lWout, lbout,
                              iWin, ibin, iWhid, ibhid, iWout, ibout);

    leaf_kernel<<<(B_ * LEAVES) / 128, NT, smem_bytes>>>(leaf_feat, curA);

    float* pin = curA;
    float* pout = curB;
    for (int d = 9; d >= 1; --d) {
        int rows = B_ << d;
        int_kernel<<<rows / 128, NT, smem_bytes>>>(int_feat, pin, pout, d, nullptr);
        float* t = pin; pin = pout; pout = t;
    }
    int_kernel<<<B_ / 128, NT, smem_bytes>>>(int_feat, pin, pout, 0, out);
}

// round 4
// speedup vs baseline: 1.7238x; 1.2807x over previous
#include <cuda_runtime.h>
#include <cuda_fp16.h>
#include <cstdint>

#define SA 136           // smem stride (halves) for activations
#define SW 136           // smem stride (halves) for weights
#define NT 1024          // 32 warps

#define B_ 512
#define LEAVES 1024
#define NINT 1023

// Weight storage (transposed [N][K], fp16 hi/lo split), filled by prep kernel
// leaf: L0 128x64=8192, L1..L4 4*16384, L5 40x128=5120  -> 78848
// int : L0 128x112=14336, L1..L4 4*16384, L5 40x128=5120 -> 84992
__device__ __align__(16) __half g_leaf_Wh[78848];
__device__ __align__(16) __half g_leaf_Wl[78848];
__device__ __align__(16) __half g_int_Wh[84992];
__device__ __align__(16) __half g_int_Wl[84992];
__device__ float  g_leaf_bias[768];   // 6 layers x 128 (padded)
__device__ float  g_int_bias[768];

// Ping-pong activation buffers for the tree (fp32, 33 channels per node)
__device__ float g_curA[(size_t)B_ * LEAVES * 33];
__device__ float g_curB[(size_t)B_ * 512 * 33];

// ---------------------------------------------------------------------------
// Prep: convert & transpose all weights to fp16 hi/lo, pad, pack biases.
// ---------------------------------------------------------------------------
__global__ void prep_kernel(
    const float* __restrict__ lWin,  const float* __restrict__ lbin,
    const float* __restrict__ lWhid, const float* __restrict__ lbhid,
    const float* __restrict__ lWout, const float* __restrict__ lbout,
    const float* __restrict__ iWin,  const float* __restrict__ ibin,
    const float* __restrict__ iWhid, const float* __restrict__ ibhid,
    const float* __restrict__ iWout, const float* __restrict__ ibout)
{
    const int total = 78848 + 84992 + 1536;
    for (int i = blockIdx.x * blockDim.x + threadIdx.x; i < total;
         i += gridDim.x * blockDim.x) {
        if (i < 78848) {
            float v;
            if (i < 8192) {                 // L0: [128][64] <- lWin[k*128+n]
                int n = i >> 6, k = i & 63;
                v = lWin[k * 128 + n];
            } else if (i < 73728) {         // L1..L4: [128][128]
                int j = i - 8192;
                int l = j >> 14;
                int w = j & 16383;
                int n = w >> 7, k = w & 127;
                v = lWhid[l * 16384 + k * 128 + n];
            } else {                        // L5: [40][128] <- lWout[k*33+n]
                int j = i - 73728;
                int n = j >> 7, k = j & 127;
                v = (n < 33) ? lWout[k * 33 + n] : 0.f;
            }
            __half h = __float2half_rn(v);
            __half lo = __float2half_rn(v - __half2float(h));
            g_leaf_Wh[i] = h; g_leaf_Wl[i] = lo;
        } else if (i < 78848 + 84992) {
            int i2 = i - 78848;
            float v;
            if (i2 < 14336) {               // L0: [128][112] <- iWin[k*128+n], k<98
                int n = i2 / 112, k = i2 - n * 112;
                v = (k < 98) ? iWin[k * 128 + n] : 0.f;
            } else if (i2 < 79872) {
                int j = i2 - 14336;
                int l = j >> 14;
                int w = j & 16383;
                int n = w >> 7, k = w & 127;
                v = iWhid[l * 16384 + k * 128 + n];
            } else {
                int j = i2 - 79872;
                int n = j >> 7, k = j & 127;
                v = (n < 33) ? iWout[k * 33 + n] : 0.f;
            }
            __half h = __float2half_rn(v);
            __half lo = __float2half_rn(v - __half2float(h));
            g_int_Wh[i2] = h; g_int_Wl[i2] = lo;
        } else {
            int i3 = i - 78848 - 84992;     // 0..1535
            int j = (i3 < 768) ? i3 : i3 - 768;
            int l = j >> 7, c = j & 127;
            float v;
            if (i3 < 768) {
                if (l == 0)      v = lbin[c];
                else if (l < 5)  v = lbhid[(l - 1) * 128 + c];
                else             v = (c < 33) ? lbout[c] : 0.f;
                g_leaf_bias[j] = v;
            } else {
                if (l == 0)      v = ibin[c];
                else if (l < 5)  v = ibhid[(l - 1) * 128 + c];
                else             v = (c < 33) ? ibout[c] : 0.f;
                g_int_bias[j] = v;
            }
        }
    }
}

// ---------------------------------------------------------------------------
// PTX helpers
// ---------------------------------------------------------------------------
__device__ __forceinline__ void mma16816(float* c, const uint32_t* a,
                                         uint32_t b0, uint32_t b1)
{
    asm volatile(
        "mma.sync.aligned.m16n8k16.row.col.f32.f16.f16.f32 "
        "{%0,%1,%2,%3}, {%4,%5,%6,%7}, {%8,%9}, {%0,%1,%2,%3};\n"
        : "+f"(c[0]), "+f"(c[1]), "+f"(c[2]), "+f"(c[3])
        : "r"(a[0]), "r"(a[1]), "r"(a[2]), "r"(a[3]), "r"(b0), "r"(b1));
}

__device__ __forceinline__ void ldsm4(uint32_t* r, uint32_t addr)
{
    asm volatile("ldmatrix.sync.aligned.m8n8.x4.shared.b16 {%0,%1,%2,%3}, [%4];"
                 : "=r"(r[0]), "=r"(r[1]), "=r"(r[2]), "=r"(r[3]) : "r"(addr));
}

__device__ __forceinline__ void cpa16(uint32_t dst, const void* src)
{
    asm volatile("cp.async.cg.shared.global [%0], [%1], 16;" :: "r"(dst), "l"(src));
}
__device__ __forceinline__ void cpa_commit() { asm volatile("cp.async.commit_group;"); }

// stage one layer's weights (hi+lo) via cp.async
__device__ __forceinline__ void stage_weights(
    uint32_t sWh, uint32_t sWl, const __half* gWh, const __half* gWl,
    int Np, int kv /* = Kp/8 */)
{
    const int Kp = kv << 3;
    const int nchunks = Np * kv;
    for (int i = threadIdx.x; i < nchunks; i += NT) {
        int r = i / kv;
        int c = (i - r * kv) << 3;
        uint32_t off = (uint32_t)(r * SW + c) * 2u;
        cpa16(sWh + off, gWh + r * Kp + c);
        cpa16(sWl + off, gWl + r * Kp + c);
    }
}

// ---------------------------------------------------------------------------
// Run a 6-layer MLP for 128 rows held in smem (hi/lo split, 3-MMA fp32 emu).
// 32 warps: warp (wm 0..7, wn 0..3) owns a 16x32 tile. cp.async double-buffered
// weights overlapped with MMA.
// ---------------------------------------------------------------------------
__device__ __forceinline__ void run_unit(
    __half* smem, const __half* gWh, const __half* gWl, const float* gbias,
    int Kp0, float* gout, float* dfinal, int row0)
{
    __half* sAh = smem;
    __half* sAl = smem + 17408;
    const uint32_t smem_u = (uint32_t)__cvta_generic_to_shared(smem);
    const uint32_t uAh = smem_u;
    const uint32_t uAl = smem_u + 17408u * 2u;
    const uint32_t uW0 = smem_u + 34816u * 2u;   // buf0: Wh then Wl
    const uint32_t uW1 = smem_u + 69632u * 2u;   // buf1

    const int tid  = threadIdx.x;
    const int warp = tid >> 5;
    const int lane = tid & 31;
    const int wm = warp >> 2;      // 0..7 (16-row block)
    const int wn = warp & 3;       // 0..3 (32-col block)
    const int gid = lane >> 2;
    const int tig = lane & 3;

    // lane-dependent ldmatrix offsets (in halves)
    // A: rows wm*16 + (lane&15), col (lane>>4)*8
    const int aRow = wm * 16 + (lane & 15);
    const int aCol = (lane >> 4) << 3;
    const uint32_t offA0 = (uint32_t)(aRow * SA + aCol) * 2u;
    // W: n = wn*32 + pair*16 + (lane>>4)*8 + (lane&7), col ((lane>>3)&1)*8
    const int wRowBase = wn * 32 + ((lane >> 4) << 3) + (lane & 7);
    const int wCol = ((lane >> 3) & 1) << 3;
    const uint32_t offW0 = (uint32_t)(wRowBase * SW + wCol) * 2u;      // pair=0
    const uint32_t offW1 = offW0 + (uint32_t)(16 * SW) * 2u;           // pair=1

    const int KpA[6] = {Kp0, 128, 128, 128, 128, 128};
    const int NpA[6] = {128, 128, 128, 128, 128, 40};

    // prologue: stage layer 0 into buf 0
    stage_weights(uW0, uW0 + 17408u * 2u, gWh, gWl, 128, Kp0 >> 3);
    cpa_commit();

    int woff = 128 * Kp0;
    #pragma unroll
    for (int l = 0; l < 6; ++l) {
        const int Kp = KpA[l];
        const int Np = NpA[l];
        const uint32_t uWbuf = (l & 1) ? uW1 : uW0;
        const uint32_t uWh = uWbuf;
        const uint32_t uWl = uWbuf + 17408u * 2u;

        if (l < 5) {
            const uint32_t uNext = (l & 1) ? uW0 : uW1;
            stage_weights(uNext, uNext + 17408u * 2u,
                          gWh + woff, gWl + woff, NpA[l + 1], KpA[l + 1] >> 3);
            cpa_commit();
            woff += NpA[l + 1] * KpA[l + 1];
            asm volatile("cp.async.wait_group 1;");
        } else {
            asm volatile("cp.async.wait_group 0;");
        }
        __syncthreads();

        // tiles this warp owns in N
        int nt_count = (Np - wn * 32 + 7) >> 3;
        if (nt_count < 0) nt_count = 0;
        if (nt_count > 4) nt_count = 4;
        const int pair_count = (nt_count + 1) >> 1;

        float C[4][4];
        #pragma unroll
        for (int nt = 0; nt < 4; ++nt)
            #pragma unroll
            for (int q = 0; q < 4; ++q) C[nt][q] = 0.f;

        if (nt_count > 0) {
            uint32_t aAh0 = uAh + offA0;
            uint32_t aAl0 = uAl + offA0;
            uint32_t aWh0 = uWh + offW0, aWh1 = uWh + offW1;
            uint32_t aWl0 = uWl + offW0, aWl1 = uWl + offW1;

            for (int k0 = 0; k0 < Kp; k0 += 16) {
                uint32_t ah[4], al[4];
                uint32_t whf[2][4], wlf[2][4];
                ldsm4(ah, aAh0);
                ldsm4(al, aAl0);
                ldsm4(whf[0], aWh0); ldsm4(wlf[0], aWl0);
                if (pair_count > 1) { ldsm4(whf[1], aWh1); ldsm4(wlf[1], aWl1); }

                #pragma unroll
                for (int nt = 0; nt < 4; ++nt) {
                    if (nt < nt_count) {
                        const int p = nt >> 1, q = (nt & 1) << 1;
                        uint32_t b0h = whf[p][q], b1h = whf[p][q + 1];
                        uint32_t b0l = wlf[p][q], b1l = wlf[p][q + 1];
                        mma16816(C[nt], ah, b0h, b1h);
                        mma16816(C[nt], ah, b0l, b1l);
                        mma16816(C[nt], al, b0h, b1h);
                    }
                }
                aAh0 += 32; aAl0 += 32;
                aWh0 += 32; aWh1 += 32; aWl0 += 32; aWl1 += 32;
            }
        }
        __syncthreads();

        // ---- epilogue ----
        if (l < 5) {
            #pragma unroll
            for (int nt = 0; nt < 4; ++nt) {
                if (nt < nt_count) {
                    int r  = wm * 16 + gid;
                    int cb = wn * 32 + nt * 8 + tig * 2;
                    float bb0 = gbias[l * 128 + cb];
                    float bb1 = gbias[l * 128 + cb + 1];
                    float v00 = fmaxf(C[nt][0] + bb0, 0.f);
                    float v01 = fmaxf(C[nt][1] + bb1, 0.f);
                    float v10 = fmaxf(C[nt][2] + bb0, 0.f);
                    float v11 = fmaxf(C[nt][3] + bb1, 0.f);
                    __half h00 = __float2half_rn(v00), h01 = __float2half_rn(v01);
                    __half h10 = __float2half_rn(v10), h11 = __float2half_rn(v11);
                    __half e00 = __float2half_rn(v00 - __half2float(h00));
                    __half e01 = __float2half_rn(v01 - __half2float(h01));
                    __half e10 = __float2half_rn(v10 - __half2float(h10));
                    __half e11 = __float2half_rn(v11 - __half2float(h11));
                    *(__half2*)(sAh + r * SA + cb)        = __halves2half2(h00, h01);
                    *(__half2*)(sAh + (r + 8) * SA + cb)  = __halves2half2(h10, h11);
                    *(__half2*)(sAl + r * SA + cb)        = __halves2half2(e00, e01);
                    *(__half2*)(sAl + (r + 8) * SA + cb)  = __halves2half2(e10, e11);
                }
            }
        } else {
            #pragma unroll
            for (int nt = 0; nt < 4; ++nt) {
                if (nt < nt_count) {
                    int r  = wm * 16 + gid;
                    int cb = wn * 32 + nt * 8 + tig * 2;
                    float bb0 = gbias[640 + cb];
                    float bb1 = gbias[640 + cb + 1];
                    float v00 = C[nt][0] + bb0;
                    float v01 = C[nt][1] + bb1;
                    float v10 = C[nt][2] + bb0;
                    float v11 = C[nt][3] + bb1;
                    if (dfinal) {
                        if (cb == 0) {
                            dfinal[row0 + r]     = v00;
                            dfinal[row0 + r + 8] = v10;
                        }
                    } else {
                        size_t ro = (size_t)(row0 + r) * 33;
                        size_t r8 = (size_t)(row0 + r + 8) * 33;
                        if (cb < 33)     { gout[ro + cb]     = v00; gout[r8 + cb]     = v10; }
                        if (cb + 1 < 33) { gout[ro + cb + 1] = v01; gout[r8 + cb + 1] = v11; }
                    }
                }
            }
        }
    }
}

// ---------------------------------------------------------------------------
// Leaf kernel: 128 rows/CTA of leaf_feat (K0=64) -> cur (33 ch, fp32)
// ---------------------------------------------------------------------------
__global__ void __launch_bounds__(NT, 1)
leaf_kernel(const float* __restrict__ leaf_feat, float* __restrict__ curOut)
{
    extern __shared__ __half smem[];
    __half* sAh = smem;
    __half* sAl = smem + 17408;

    const int row0 = blockIdx.x * 128;

    for (int i = threadIdx.x; i < 128 * 16; i += NT) {
        int r = i >> 4, c4 = i & 15;
        float4 v = ((const float4*)(leaf_feat + (size_t)(row0 + r) * 64))[c4];
        int c = c4 * 4;
        __half h0 = __float2half_rn(v.x), h1 = __float2half_rn(v.y);
        __half h2 = __float2half_rn(v.z), h3 = __float2half_rn(v.w);
        __half e0 = __float2half_rn(v.x - __half2float(h0));
        __half e1 = __float2half_rn(v.y - __half2float(h1));
        __half e2 = __float2half_rn(v.z - __half2float(h2));
        __half e3 = __float2half_rn(v.w - __half2float(h3));
        *(__half2*)(sAh + r * SA + c)     = __halves2half2(h0, h1);
        *(__half2*)(sAh + r * SA + c + 2) = __halves2half2(h2, h3);
        *(__half2*)(sAl + r * SA + c)     = __halves2half2(e0, e1);
        *(__half2*)(sAl + r * SA + c + 2) = __halves2half2(e2, e3);
    }

    run_unit(smem, g_leaf_Wh, g_leaf_Wl, g_leaf_bias, 64, curOut, nullptr, row0);
}

// ---------------------------------------------------------------------------
// Tree-level kernel: builds [feat(32) | child0(33) | child1(33) | pad] rows
// ---------------------------------------------------------------------------
__global__ void __launch_bounds__(NT, 1)
int_kernel(const float* __restrict__ int_feat, const float* __restrict__ prev,
           float* __restrict__ curOut, int log2n, float* dfinal)
{
    extern __shared__ __half smem[];
    __half* sAh = smem;
    __half* sAl = smem + 17408;

    const int row0 = blockIdx.x * 128;
    const int n = 1 << log2n;

    for (int i = threadIdx.x; i < 128 * 112; i += NT) {
        int r = i / 112, c = i - r * 112;
        int rowg = row0 + r;
        int b  = rowg >> log2n;
        int ii = rowg & (n - 1);
        float v;
        if (c < 32) {
            v = int_feat[((size_t)b * NINT + (n - 1) + ii) * 32 + c];
        } else if (c < 98) {
            v = prev[((size_t)b * (n << 1) + (ii << 1)) * 33 + (c - 32)];
        } else {
            v = 0.f;
        }
        __half h = __float2half_rn(v);
        __half e = __float2half_rn(v - __half2float(h));
        sAh[r * SA + c] = h;
        sAl[r * SA + c] = e;
    }

    run_unit(smem, g_int_Wh, g_int_Wl, g_int_bias, 112, curOut, dfinal, row0);
}

// ---------------------------------------------------------------------------
extern "C" void kernel_launch(void* const* d_in, const int* in_sizes, int n_in,
                              void* d_out, int out_size)
{
    const float* leaf_feat = (const float*)d_in[0];
    const float* int_feat  = (const float*)d_in[1];
    const float* lWin  = (const float*)d_in[2];
    const float* lbin  = (const float*)d_in[3];
    const float* lWhid = (const float*)d_in[4];
    const float* lbhid = (const float*)d_in[5];
    const float* lWout = (const float*)d_in[6];
    const float* lbout = (const float*)d_in[7];
    const float* iWin  = (const float*)d_in[8];
    const float* ibin  = (const float*)d_in[9];
    const float* iWhid = (const float*)d_in[10];
    const float* ibhid = (const float*)d_in[11];
    const float* iWout = (const float*)d_in[12];
    const float* ibout = (const float*)d_in[13];
    float* out = (float*)d_out;

    // smem: act (2*17408) + weights double-buffered (2*34816) halves
    const int smem_bytes = (2 * 17408 + 2 * 34816) * (int)sizeof(__half); // 208896
    cudaFuncSetAttribute(leaf_kernel, cudaFuncAttributeMaxDynamicSharedMemorySize, smem_bytes);
    cudaFuncSetAttribute(int_kernel,  cudaFuncAttributeMaxDynamicSharedMemorySize, smem_bytes);

    float *curA = nullptr, *curB = nullptr;
    cudaGetSymbolAddress((void**)&curA, g_curA);
    cudaGetSymbolAddress((void**)&curB, g_curB);

    prep_kernel<<<256, 256>>>(lWin, lbin, lWhid, lbhid, lWout, lbout,
                              iWin, ibin, iWhid, ibhid, iWout, ibout);

    leaf_kernel<<<(B_ * LEAVES) / 128, NT, smem_bytes>>>(leaf_feat, curA);

    float* pin = curA;
    float* pout = curB;
    for (int d = 9; d >= 1; --d) {
        int rows = B_ << d;
        int_kernel<<<rows / 128, NT, smem_bytes>>>(int_feat, pin, pout, d, nullptr);
        float* t = pin; pin = pout; pout = t;
    }
    int_kernel<<<B_ / 128, NT, smem_bytes>>>(int_feat, pin, pout, 0, out);
}